// round 2
// baseline (speedup 1.0000x reference)
#include <cuda_runtime.h>
#include <math.h>

#define BB 16
#define NN 4096
#define MM 1024
#define CF 64
#define INCH 67
#define GRPS (BB*MM)          // 16384 centroids total
#define XYZ_OUT ((size_t)BB*MM*3)

// ---------------- device scratch (no allocations allowed) ----------------
__device__ int   g_nbr[(16+32+64)*GRPS];          // neighbor idx, 3 scales packed
__device__ float g_x0[(size_t)64 * GRPS * 64];    // layer-0 activations scratch (256MB)
__device__ float g_rawmax[128 * GRPS];            // raw layer-1 max per (c, centroid)
__device__ float g_rawmin[128 * GRPS];            // raw layer-1 min per (c, centroid)
__device__ float g_stats[512];                    // [0:64)sum0 [128:192)sumsq0 [256:384)sum1 [384:512)sumsq1

__device__ __forceinline__ float sqdist_rn(float dx, float dy, float dz){
    // plain mul/add, no FMA contraction (match XLA elementwise square+sum)
    return __fadd_rn(__fadd_rn(__fmul_rn(dx,dx),__fmul_rn(dy,dy)),__fmul_rn(dz,dz));
}
__device__ __forceinline__ float gelu_exact(float x){
    return 0.5f * x * (1.0f + erff(x * 0.70710678118654752f));
}

// ---------------- 1) farthest point sampling ----------------
__global__ void fps_kernel(const float* __restrict__ xyz, float* __restrict__ out_newxyz){
    extern __shared__ float sm[];
    float* sx = sm; float* sy = sm+NN; float* sz = sm+2*NN; float* sd = sm+3*NN;
    __shared__ float rv[32]; __shared__ int ri[32];
    int b = blockIdx.x, t = threadIdx.x;
    for (int i=t;i<NN;i+=blockDim.x){
        const float* p = xyz + ((size_t)b*NN+i)*3;
        sx[i]=p[0]; sy[i]=p[1]; sz[i]=p[2]; sd[i]=1e10f;
    }
    __syncthreads();
    int far = 0;
    for (int it=0; it<MM; it++){
        float cx=sx[far], cy=sy[far], cz=sz[far];
        if (t==0){
            float* o = out_newxyz + ((size_t)b*MM+it)*3;
            o[0]=cx; o[1]=cy; o[2]=cz;
        }
        float best=-1.0f; int bi=0;
        for (int i=t;i<NN;i+=blockDim.x){
            float d  = sqdist_rn(sx[i]-cx, sy[i]-cy, sz[i]-cz);
            float nd = fminf(sd[i], d);
            sd[i]=nd;
            if (nd>best){ best=nd; bi=i; }   // strict > keeps smallest index on ties
        }
        #pragma unroll
        for (int o=16;o;o>>=1){
            float ov=__shfl_down_sync(0xffffffffu,best,o);
            int   oi=__shfl_down_sync(0xffffffffu,bi,o);
            if (ov>best || (ov==best && oi<bi)){ best=ov; bi=oi; }
        }
        if ((t&31)==0){ rv[t>>5]=best; ri[t>>5]=bi; }
        __syncthreads();
        if (t<32){
            best=rv[t]; bi=ri[t];
            #pragma unroll
            for (int o=16;o;o>>=1){
                float ov=__shfl_down_sync(0xffffffffu,best,o);
                int   oi=__shfl_down_sync(0xffffffffu,bi,o);
                if (ov>best || (ov==best && oi<bi)){ best=ov; bi=oi; }
            }
            if (t==0) ri[0]=bi;
        }
        __syncthreads();
        far = ri[0];
        __syncthreads();
    }
}

// ---------------- 2) ball query: one warp per centroid, all 3 scales ----------------
__global__ void ballq_kernel(const float* __restrict__ xyz, const float* __restrict__ newxyz){
    int gw   = (blockIdx.x*blockDim.x + threadIdx.x)>>5;
    int lane = threadIdx.x & 31;
    if (gw >= GRPS) return;
    int b = gw >> 10;
    float cx=newxyz[gw*3+0], cy=newxyz[gw*3+1], cz=newxyz[gw*3+2];
    const float R2_0=(float)(0.1*0.1), R2_1=(float)(0.2*0.2), R2_2=(float)(0.4*0.4);
    int c0=0,c1=0,c2=0, f0=0,f1=0,f2=0;
    int* n0 = g_nbr + gw*16;
    int* n1 = g_nbr + 16*GRPS + gw*32;
    int* n2 = g_nbr + 48*GRPS + gw*64;
    const float* base = xyz + (size_t)b*NN*3;
    for (int s=0;s<NN;s+=32){
        int i = s + lane;
        float d = sqdist_rn(base[i*3+0]-cx, base[i*3+1]-cy, base[i*3+2]-cz);
        unsigned m0=__ballot_sync(0xffffffffu, d<=R2_0);
        unsigned m1=__ballot_sync(0xffffffffu, d<=R2_1);
        unsigned m2=__ballot_sync(0xffffffffu, d<=R2_2);
        if (m0 && c0<16){
            if (c0==0) f0 = s + __ffs(m0) - 1;
            int r = __popc(m0 & ((1u<<lane)-1u));
            if ((m0>>lane)&1u){ if (c0+r<16) n0[c0+r]=i; }
            c0 += __popc(m0); if (c0>16) c0=16;
        }
        if (m1 && c1<32){
            if (c1==0) f1 = s + __ffs(m1) - 1;
            int r = __popc(m1 & ((1u<<lane)-1u));
            if ((m1>>lane)&1u){ if (c1+r<32) n1[c1+r]=i; }
            c1 += __popc(m1); if (c1>32) c1=32;
        }
        if (m2 && c2<64){
            if (c2==0) f2 = s + __ffs(m2) - 1;
            int r = __popc(m2 & ((1u<<lane)-1u));
            if ((m2>>lane)&1u){ if (c2+r<64) n2[c2+r]=i; }
            c2 += __popc(m2); if (c2>64) c2=64;
        }
        if (c0>=16 && c1>=32 && c2>=64) break;
    }
    for (int j=c0+lane;j<16;j+=32) n0[j]=f0;
    for (int j=c1+lane;j<32;j+=32) n1[j]=f1;
    for (int j=c2+lane;j<64;j+=32) n2[j]=f2;
}

// ---------------- stats zeroing ----------------
__global__ void zero_stats_kernel(){ g_stats[threadIdx.x] = 0.0f; }

// ---------------- 3a) pass A: gather + conv0, accumulate stats0, store X0 ----------------
template<int K,int C0>
__global__ void __launch_bounds__(256)
passA_kernel(const float* __restrict__ xyz, const float* __restrict__ feat,
             const float* __restrict__ newxyz, int noff,
             const float* __restrict__ w0)
{
    const int P = GRPS*K;
    constexpr int SP = 132;
    extern __shared__ float sm[];
    float* in_s = sm;                  // INCH * SP
    float* w0s  = sm + INCH*SP;        // INCH * C0 (transposed)
    float* st   = w0s + INCH*C0;       // 2*C0
    int tid = threadIdx.x;
    int tp  = blockIdx.x*128;

    for (int i=tid;i<C0*INCH;i+=256){ int c=i/INCH, kk=i-c*INCH; w0s[kk*C0+c]=w0[i]; }
    for (int i=tid;i<2*C0;i+=256) st[i]=0.0f;

    { // gather: 2 threads per point
        int p  = tid>>1, h = tid&1;
        int gp = tp + p;
        int g  = gp / K;
        int idx = g_nbr[noff + gp];
        int b   = g >> 10;
        const float* fs = feat + ((size_t)(b*NN)+idx)*CF;
        if (h==0){
            const float* xs = xyz + ((size_t)(b*NN)+idx)*3;
            in_s[0*SP+p] = xs[0]-newxyz[g*3+0];
            in_s[1*SP+p] = xs[1]-newxyz[g*3+1];
            in_s[2*SP+p] = xs[2]-newxyz[g*3+2];
            #pragma unroll
            for (int q=0;q<8;q++){
                float4 v = *(const float4*)(fs + q*4);
                in_s[(3+q*4+0)*SP+p]=v.x; in_s[(3+q*4+1)*SP+p]=v.y;
                in_s[(3+q*4+2)*SP+p]=v.z; in_s[(3+q*4+3)*SP+p]=v.w;
            }
        } else {
            #pragma unroll
            for (int q=8;q<16;q++){
                float4 v = *(const float4*)(fs + q*4);
                in_s[(3+q*4+0)*SP+p]=v.x; in_s[(3+q*4+1)*SP+p]=v.y;
                in_s[(3+q*4+2)*SP+p]=v.z; in_s[(3+q*4+3)*SP+p]=v.w;
            }
        }
    }
    __syncthreads();

    int tx = tid&15, ty = tid>>4;
    constexpr int JC = C0/16;
    float acc[JC][8];
    #pragma unroll
    for (int j=0;j<JC;j++)
        #pragma unroll
        for (int i=0;i<8;i++) acc[j][i]=0.0f;

    for (int kk=0;kk<INCH;kk++){
        float av[JC], bv[8];
        #pragma unroll
        for (int j=0;j<JC;j++) av[j]=w0s[kk*C0 + ty+16*j];
        #pragma unroll
        for (int i=0;i<8;i++)  bv[i]=in_s[kk*SP + tx+16*i];
        #pragma unroll
        for (int j=0;j<JC;j++)
            #pragma unroll
            for (int i=0;i<8;i++) acc[j][i]=fmaf(av[j],bv[i],acc[j][i]);
    }

    #pragma unroll
    for (int j=0;j<JC;j++){
        int c = ty+16*j;
        float s=0.0f, s2=0.0f;
        float* dst = g_x0 + (size_t)c*P + tp;
        #pragma unroll
        for (int i=0;i<8;i++){
            float v=acc[j][i];
            s+=v; s2+=v*v;
            dst[tx+16*i]=v;
        }
        atomicAdd(&st[c],     s);
        atomicAdd(&st[C0+c],  s2);
    }
    __syncthreads();
    for (int i=tid;i<C0;i+=256){
        atomicAdd(&g_stats[i],     st[i]);
        atomicAdd(&g_stats[128+i], st[C0+i]);
    }
}

// ---------------- 3b) pass C: norm+gelu(X0) -> conv1 -> min/max over k + stats1 ----------------
template<int K,int C0,int C1>
__global__ void __launch_bounds__(256)
passC_kernel(const float* __restrict__ w1,
             const float* __restrict__ g0v, const float* __restrict__ b0v)
{
    const int P = GRPS*K;
    extern __shared__ float sm[];
    float* gs  = sm;                  // C0 * 128
    float* w1s = gs + C0*128;         // C0 * C1 (transposed)
    float* ab  = w1s + C0*C1;         // 2*C0  (a0, b0)
    float* st  = ab + 2*C0;           // 2*C1
    int tid = threadIdx.x, tp = blockIdx.x*128;

    if (tid < C0){
        float cnt  = (float)P;
        float mean = g_stats[tid]/cnt;
        float var  = g_stats[128+tid]/cnt - mean*mean;
        float a    = g0v[tid]/sqrtf(var + 1e-5f);
        ab[tid]    = a;
        ab[C0+tid] = b0v[tid] - mean*a;
    }
    for (int i=tid;i<C1*C0;i+=256){ int c1=i/C0, kk=i-c1*C0; w1s[kk*C1+c1]=w1[i]; }
    for (int i=tid;i<2*C1;i+=256) st[i]=0.0f;
    __syncthreads();

    for (int i=tid;i<C0*128;i+=256){
        int c=i>>7, p=i&127;
        float v = g_x0[(size_t)c*P + tp + p];
        v = ab[c]*v + ab[C0+c];
        gs[c*128+p] = gelu_exact(v);
    }
    __syncthreads();

    int tx = tid&15, ty = tid>>4;
    constexpr int JC = C1/16;
    float acc[JC][8];
    #pragma unroll
    for (int j=0;j<JC;j++)
        #pragma unroll
        for (int i=0;i<8;i++) acc[j][i]=0.0f;

    for (int kk=0;kk<C0;kk++){
        float av[JC], bv[8];
        #pragma unroll
        for (int j=0;j<JC;j++) av[j]=w1s[kk*C1 + ty+16*j];
        #pragma unroll
        for (int i=0;i<8;i++)  bv[i]=gs[kk*128 + tx+16*i];
        #pragma unroll
        for (int j=0;j<JC;j++)
            #pragma unroll
            for (int i=0;i<8;i++) acc[j][i]=fmaf(av[j],bv[i],acc[j][i]);
    }

    constexpr int IPG = K/16;     // accumulator i's per k-group
    constexpr int GPT = 128/K;    // groups (centroids) per tile
    int gbase = tp / K;
    #pragma unroll
    for (int j=0;j<JC;j++){
        int c = ty+16*j;
        float s=0.0f, s2=0.0f;
        #pragma unroll
        for (int i=0;i<8;i++){ float v=acc[j][i]; s+=v; s2+=v*v; }
        atomicAdd(&st[c],    s);
        atomicAdd(&st[C1+c], s2);
        #pragma unroll
        for (int g=0; g<GPT; g++){
            float mx = -3.4e38f, mn = 3.4e38f;
            #pragma unroll
            for (int u=0;u<IPG;u++){
                mx = fmaxf(mx, acc[j][g*IPG+u]);
                mn = fminf(mn, acc[j][g*IPG+u]);
            }
            #pragma unroll
            for (int o=8;o>=1;o>>=1){
                mx = fmaxf(mx, __shfl_xor_sync(0xffffffffu,mx,o));
                mn = fminf(mn, __shfl_xor_sync(0xffffffffu,mn,o));
            }
            if (tx==0){
                g_rawmax[c*GRPS + gbase + g] = mx;
                g_rawmin[c*GRPS + gbase + g] = mn;
            }
        }
    }
    __syncthreads();
    for (int i=tid;i<C1;i+=256){
        atomicAdd(&g_stats[256+i], st[i]);
        atomicAdd(&g_stats[384+i], st[C1+i]);
    }
}

// ---------------- 3c) finalize: normalize min/max + gelu -> output slice ----------------
// gelu is quasiconvex (valley at x ~ -0.75), so max over a set of gelu values is
// attained at the set's min or max; BN affine has positive scale so order is kept.
template<int K,int C1>
__global__ void out_kernel(const float* __restrict__ g1v, const float* __restrict__ b1v,
                           float* __restrict__ out, int chOff)
{
    int i = blockIdx.x*blockDim.x + threadIdx.x;
    if (i >= C1*GRPS) return;
    int c = i / GRPS; int g = i - c*GRPS;
    int b = g >> 10, m = g & 1023;
    float cnt  = (float)(GRPS*K);
    float mean = g_stats[256+c]/cnt;
    float var  = g_stats[384+c]/cnt - mean*mean;
    float a    = g1v[c]/sqrtf(var + 1e-5f);
    float bb   = b1v[c] - mean*a;
    float v1   = a*g_rawmax[c*GRPS + g] + bb;
    float v2   = a*g_rawmin[c*GRPS + g] + bb;
    out[XYZ_OUT + ((size_t)b*320 + chOff + c)*MM + m] = fmaxf(gelu_exact(v1), gelu_exact(v2));
}

// ---------------- launch ----------------
extern "C" void kernel_launch(void* const* d_in, const int* in_sizes, int n_in,
                              void* d_out, int out_size)
{
    // setup_inputs dict insertion order:
    // xyz, features, w00, w01, w10, w11, w20, w21,
    // then INTERLEAVED per layer: g00,b00, g01,b01, g10,b10, g11,b11, g20,b20, g21,b21
    const float* xyz  = (const float*)d_in[0];
    const float* feat = (const float*)d_in[1];
    const float* w00  = (const float*)d_in[2];
    const float* w01  = (const float*)d_in[3];
    const float* w10  = (const float*)d_in[4];
    const float* w11  = (const float*)d_in[5];
    const float* w20  = (const float*)d_in[6];
    const float* w21  = (const float*)d_in[7];
    const float* g00  = (const float*)d_in[8];
    const float* b00  = (const float*)d_in[9];
    const float* g01  = (const float*)d_in[10];
    const float* b01  = (const float*)d_in[11];
    const float* g10  = (const float*)d_in[12];
    const float* b10  = (const float*)d_in[13];
    const float* g11  = (const float*)d_in[14];
    const float* b11  = (const float*)d_in[15];
    const float* g20  = (const float*)d_in[16];
    const float* b20  = (const float*)d_in[17];
    const float* g21  = (const float*)d_in[18];
    const float* b21  = (const float*)d_in[19];
    float* out = (float*)d_out;
    float* newxyz = out;   // first B*M*3 floats of output ARE new_xyz

    const int smFPS   = 4*NN*4;
    const int smA32   = (INCH*132 + INCH*32 + 2*32)*4;
    const int smA64   = (INCH*132 + INCH*64 + 2*64)*4;
    const int smC0    = (32*128 + 32*64  + 2*32 + 2*64 )*4;
    const int smC12   = (64*128 + 64*128 + 2*64 + 2*128)*4;

    cudaFuncSetAttribute(fps_kernel,            cudaFuncAttributeMaxDynamicSharedMemorySize, smFPS);
    cudaFuncSetAttribute(passA_kernel<16,32>,   cudaFuncAttributeMaxDynamicSharedMemorySize, smA32);
    cudaFuncSetAttribute(passA_kernel<32,64>,   cudaFuncAttributeMaxDynamicSharedMemorySize, smA64);
    cudaFuncSetAttribute(passA_kernel<64,64>,   cudaFuncAttributeMaxDynamicSharedMemorySize, smA64);
    cudaFuncSetAttribute(passC_kernel<16,32,64>,  cudaFuncAttributeMaxDynamicSharedMemorySize, smC0);
    cudaFuncSetAttribute(passC_kernel<32,64,128>, cudaFuncAttributeMaxDynamicSharedMemorySize, smC12);
    cudaFuncSetAttribute(passC_kernel<64,64,128>, cudaFuncAttributeMaxDynamicSharedMemorySize, smC12);

    fps_kernel<<<BB, 1024, smFPS>>>(xyz, newxyz);
    ballq_kernel<<<(GRPS*32)/256, 256>>>(xyz, newxyz);

    // ---- scale 0: k=16, C0=32, C1=64, channel offset 0
    zero_stats_kernel<<<1,512>>>();
    passA_kernel<16,32><<<GRPS*16/128, 256, smA32>>>(xyz, feat, newxyz, 0, w00);
    passC_kernel<16,32,64><<<GRPS*16/128, 256, smC0>>>(w01, g00, b00);
    out_kernel<16,64><<<(64*GRPS)/256, 256>>>(g01, b01, out, 0);

    // ---- scale 1: k=32, C0=64, C1=128, channel offset 64
    zero_stats_kernel<<<1,512>>>();
    passA_kernel<32,64><<<GRPS*32/128, 256, smA64>>>(xyz, feat, newxyz, 16*GRPS, w10);
    passC_kernel<32,64,128><<<GRPS*32/128, 256, smC12>>>(w11, g10, b10);
    out_kernel<32,128><<<(128*GRPS)/256, 256>>>(g11, b11, out, 64);

    // ---- scale 2: k=64, C0=64, C1=128, channel offset 192
    zero_stats_kernel<<<1,512>>>();
    passA_kernel<64,64><<<GRPS*64/128, 256, smA64>>>(xyz, feat, newxyz, 48*GRPS, w20);
    passC_kernel<64,64,128><<<GRPS*64/128, 256, smC12>>>(w21, g20, b20);
    out_kernel<64,128><<<(128*GRPS)/256, 256>>>(g21, b21, out, 192);
}